// round 8
// baseline (speedup 1.0000x reference)
#include <cuda_runtime.h>
#include <cstdint>
#include <cstddef>

#define M_TOK 8192
#define INF   4096
#define OUTF  4096
#define RK    16
#define BM    128
#define BN    128
#define BKB   128                 // K-bytes per stage (int8)
#define KITERS (INF / BKB)        // 32
#define STAGES 4
#define A_BYTES (BM * BKB)        // 16384
#define STAGE_BYTES (2 * A_BYTES) // 32768 (A tile + B tile)
#define SMEM_DYN (STAGES * STAGE_BYTES)  // 131072

// ---- device scratch (no allocation allowed) ----
__device__ float g_T[(size_t)M_TOK * RK];                 // LoRA intermediate
__device__ __align__(16) int8_t g_x8[(size_t)M_TOK * INF];   // canonical int8 x
__device__ __align__(16) int8_t g_w8[(size_t)OUTF * INF];    // canonical int8 w
__device__ int g_fmt_x, g_fmt_w;                          // 1 if source is int32-encoded

// ---------------- helpers ----------------
static __device__ __forceinline__ uint32_t smem_u32(const void* p) {
    uint32_t a;
    asm("{ .reg .u64 t; cvta.to.shared.u64 t, %1; cvt.u32.u64 %0, t; }" : "=r"(a) : "l"(p));
    return a;
}
static __device__ __forceinline__ uint32_t swz128(uint32_t off) {
    return off ^ ((off >> 3) & 0x70);
}
static __device__ __forceinline__ void cp16(uint32_t d, const void* s) {
    asm volatile("cp.async.cg.shared.global [%0], [%1], 16;" :: "r"(d), "l"(s) : "memory");
}
#define CP_COMMIT() asm volatile("cp.async.commit_group;" ::: "memory")
#define CP_WAIT(n)  asm volatile("cp.async.wait_group %0;" :: "n"(n) : "memory")

static __device__ __forceinline__ uint32_t lds32(uint32_t a) {
    uint32_t v;
    asm volatile("ld.shared.b32 %0, [%1];" : "=r"(v) : "r"(a));
    return v;
}
static __device__ __forceinline__ void imma(int& d0, int& d1, int& d2, int& d3,
                                            uint32_t a0, uint32_t a1, uint32_t a2, uint32_t a3,
                                            uint32_t b0, uint32_t b1) {
    asm volatile(
        "mma.sync.aligned.m16n8k32.row.col.s32.s8.s8.s32 "
        "{%0,%1,%2,%3}, {%4,%5,%6,%7}, {%8,%9}, {%0,%1,%2,%3};"
        : "+r"(d0), "+r"(d1), "+r"(d2), "+r"(d3)
        : "r"(a0), "r"(a1), "r"(a2), "r"(a3), "r"(b0), "r"(b1));
}

// ---------------- dtype detection ----------------
// If int8 data was promoted to int32 by the harness, every int32 word lies in
// [-127, 127]. If the buffer really is packed int8, an int32 view is ~uniform
// 32-bit noise (P(|v|<=300) ~ 1e-7). 4096 samples, majority vote.
__global__ void __launch_bounds__(256) detect_kernel(const void* xp, const void* wp) {
    __shared__ int cx[256], cw[256];
    const int t = threadIdx.x;
    const int* xi = (const int*)xp;
    const int* wi = (const int*)wp;
    int lx = 0, lw = 0;
#pragma unroll
    for (int j = 0; j < 16; j++) {
        unsigned s = (unsigned)(t * 16 + j) * 2654435761u;
        int v = xi[s & 8388607];         // < 8M int32 slots valid under both encodings
        lx += (v >= -300 && v <= 300);
        int w = wi[s & 4194303];         // < 4M int32 slots valid under both encodings
        lw += (w >= -300 && w <= 300);
    }
    cx[t] = lx; cw[t] = lw;
    __syncthreads();
    if (t == 0) {
        int sx = 0, sw = 0;
        for (int i = 0; i < 256; i++) { sx += cx[i]; sw += cw[i]; }
        g_fmt_x = (sx > 2048);
        g_fmt_w = (sw > 2048);
    }
}

// ---------------- pack to canonical int8 ----------------
__global__ void __launch_bounds__(256) pack_kernel(int8_t* __restrict__ dst,
                                                   const void* __restrict__ src,
                                                   int n_c4, int which) {
    const int fmt = which ? g_fmt_w : g_fmt_x;
    const int i = blockIdx.x * blockDim.x + threadIdx.x;
    if (i >= n_c4) return;
    char4 c;
    if (fmt) {
        int4 v = ((const int4*)src)[i];
        c.x = (char)v.x; c.y = (char)v.y; c.z = (char)v.z; c.w = (char)v.w;
    } else {
        c = ((const char4*)src)[i];
    }
    ((char4*)dst)[i] = c;
}

// ---------------- prep: T[m][r] = sum_k x[m][k] * lora_a[r][k]  (fp32) ------
__global__ void __launch_bounds__(256) prep_t_kernel(const float* __restrict__ la) {
    const int wid = threadIdx.x >> 5, lane = threadIdx.x & 31;
    const int m = blockIdx.x * 8 + wid;
    const int8_t* __restrict__ xr = g_x8 + (size_t)m * INF;

    float acc[RK];
#pragma unroll
    for (int r = 0; r < RK; r++) acc[r] = 0.f;

    for (int j = 0; j < 32; j++) {
        const int k0 = j * 128 + lane * 4;
        char4 c = *(const char4*)(xr + k0);
        const float f0 = (float)c.x, f1 = (float)c.y, f2 = (float)c.z, f3 = (float)c.w;
#pragma unroll
        for (int r = 0; r < RK; r++) {
            float4 a = *(const float4*)(la + (size_t)r * INF + k0);
            acc[r] = fmaf(f0, a.x, acc[r]);
            acc[r] = fmaf(f1, a.y, acc[r]);
            acc[r] = fmaf(f2, a.z, acc[r]);
            acc[r] = fmaf(f3, a.w, acc[r]);
        }
    }
#pragma unroll
    for (int off = 16; off >= 1; off >>= 1)
#pragma unroll
        for (int r = 0; r < RK; r++)
            acc[r] += __shfl_xor_sync(0xffffffffu, acc[r], off);
    if (lane == 0) {
#pragma unroll
        for (int r = 0; r < RK; r++) g_T[(size_t)m * RK + r] = acc[r];
    }
}

// ---------------- main: int8 IMMA GEMM + fused LoRA/bias/GELU epilogue -----
static __device__ __forceinline__ void load_stage(uint32_t base, int m0, int n0, int kt, int t) {
    const int8_t* __restrict__ gA = g_x8 + (size_t)m0 * INF + kt * BKB;
    const int8_t* __restrict__ gB = g_w8 + (size_t)n0 * INF + kt * BKB;
#pragma unroll
    for (int i = 0; i < 4; i++) {
        int c = t + 256 * i;                      // 0..1023
        int row = c >> 3, j = c & 7;
        cp16(base + swz128((uint32_t)(row * 128 + j * 16)),
             (const void*)(gA + (size_t)row * INF + j * 16));
    }
#pragma unroll
    for (int i = 0; i < 4; i++) {
        int c = t + 256 * i;
        int row = c >> 3, j = c & 7;
        cp16(base + (uint32_t)A_BYTES + swz128((uint32_t)(row * 128 + j * 16)),
             (const void*)(gB + (size_t)row * INF + j * 16));
    }
}

__global__ void __launch_bounds__(256, 1)
gemm_kernel(float* __restrict__ out,
            const float* __restrict__ xsc, const float* __restrict__ wsc,
            const float* __restrict__ bias, const float* __restrict__ lora_b,
            const unsigned int* __restrict__ fgp) {
    extern __shared__ __align__(1024) unsigned char dsm[];

    const int t = threadIdx.x;
    const int wid = t >> 5, lane = t & 31;
    const int g = lane >> 2, tig = lane & 3;      // mma fragment coords
    const int wm = wid & 3, wn = wid >> 2;        // 4 warps in M, 2 in N
    const int m_warp = wm * 32, n_warp = wn * 64;
    const int n0 = blockIdx.x * BN, m0 = blockIdx.y * BM;

    const uint32_t smem0 = smem_u32(dsm);

    int c[2][8][4];
#pragma unroll
    for (int am = 0; am < 2; am++)
#pragma unroll
        for (int na = 0; na < 8; na++)
#pragma unroll
            for (int f = 0; f < 4; f++) c[am][na][f] = 0;

#pragma unroll
    for (int s = 0; s < 3; s++) {
        load_stage(smem0 + s * STAGE_BYTES, m0, n0, s, t);
        CP_COMMIT();
    }

    for (int kt = 0; kt < KITERS; kt++) {
        CP_WAIT(2);
        __syncthreads();

        const uint32_t sA = smem0 + (uint32_t)(kt & 3) * STAGE_BYTES;
        const uint32_t sB = sA + (uint32_t)A_BYTES;

#pragma unroll
        for (int ks = 0; ks < 4; ks++) {
            const int kb = ks * 32 + tig * 4;

            // PTX mma.m16n8k32.s8 A fragment:
            //  a0:(row g, k kb) a1:(row g+8, k kb) a2:(row g, kb+16) a3:(row g+8, kb+16)
            uint32_t a[2][4];
#pragma unroll
            for (int am = 0; am < 2; am++) {
                const int r0 = m_warp + am * 16 + g;
                a[am][0] = lds32(sA + swz128((uint32_t)(r0 * 128 + kb)));
                a[am][1] = lds32(sA + swz128((uint32_t)((r0 + 8) * 128 + kb)));
                a[am][2] = lds32(sA + swz128((uint32_t)(r0 * 128 + kb + 16)));
                a[am][3] = lds32(sA + swz128((uint32_t)((r0 + 8) * 128 + kb + 16)));
            }
            uint32_t b[8][2];
#pragma unroll
            for (int na = 0; na < 8; na++) {
                const int nr = n_warp + na * 8 + g;
                b[na][0] = lds32(sB + swz128((uint32_t)(nr * 128 + kb)));
                b[na][1] = lds32(sB + swz128((uint32_t)(nr * 128 + kb + 16)));
            }
#pragma unroll
            for (int am = 0; am < 2; am++)
#pragma unroll
                for (int na = 0; na < 8; na++)
                    imma(c[am][na][0], c[am][na][1], c[am][na][2], c[am][na][3],
                         a[am][0], a[am][1], a[am][2], a[am][3],
                         b[na][0], b[na][1]);
        }

        if (kt + 3 < KITERS) {
            __syncthreads();
            load_stage(smem0 + (uint32_t)((kt + 3) & 3) * STAGE_BYTES, m0, n0, kt + 3, t);
        }
        CP_COMMIT();
    }

    CP_WAIT(0);
    __syncthreads();

    // ---- epilogue smem: reuse pipeline buffers ----
    float* Ts   = (float*)dsm;                    // [128][16]
    float* Bs   = (float*)(dsm + 8192);           // [128][16]
    float* s_xs = (float*)(dsm + 16384);
    float* s_ws = (float*)(dsm + 16896);
    float* s_bs = (float*)(dsm + 17408);

    {
        const float4* tg = (const float4*)(g_T + (size_t)m0 * RK);
        const float4* bg = (const float4*)(lora_b + (size_t)n0 * RK);
        float4* ts4 = (float4*)Ts;
        float4* bs4 = (float4*)Bs;
#pragma unroll
        for (int i = 0; i < 2; i++) {
            ts4[t + 256 * i] = tg[t + 256 * i];
            bs4[t + 256 * i] = bg[t + 256 * i];
        }
        if (t < 128) {
            s_xs[t] = xsc[m0 + t];
            s_ws[t] = wsc[n0 + t];
            s_bs[t] = bias[n0 + t];
        }
    }
    __syncthreads();

    // fuse_gelu: nonzero 32-bit word under ANY encoding (int 1, float 1.0f);
    // if the flag input wasn't provided, default to enabled (reference setup uses 1).
    const bool fg = fgp ? (fgp[0] != 0u) : true;

#pragma unroll
    for (int i = 0; i < 4; i++) {
        const int rowT = m_warp + i * 8 + g;
        const float xsv = s_xs[rowT];
        const float4* tp = (const float4*)(Ts + rowT * 16);
        const float4 t0 = tp[0], t1 = tp[1], t2 = tp[2], t3 = tp[3];
        float* __restrict__ orow = out + (size_t)(m0 + rowT) * OUTF + n0;

#pragma unroll
        for (int na = 0; na < 8; na++) {
            const int colb = n_warp + na * 8 + 2 * tig;
            float v2[2];
#pragma unroll
            for (int cp = 0; cp < 2; cp++) {
                const int col = colb + cp;
                const float4* bp = (const float4*)(Bs + col * 16);
                const float4 b0 = bp[0], b1 = bp[1], b2 = bp[2], b3 = bp[3];
                float lora = t0.x * b0.x;
                lora = fmaf(t0.y, b0.y, lora); lora = fmaf(t0.z, b0.z, lora);
                lora = fmaf(t0.w, b0.w, lora); lora = fmaf(t1.x, b1.x, lora);
                lora = fmaf(t1.y, b1.y, lora); lora = fmaf(t1.z, b1.z, lora);
                lora = fmaf(t1.w, b1.w, lora); lora = fmaf(t2.x, b2.x, lora);
                lora = fmaf(t2.y, b2.y, lora); lora = fmaf(t2.z, b2.z, lora);
                lora = fmaf(t2.w, b2.w, lora); lora = fmaf(t3.x, b3.x, lora);
                lora = fmaf(t3.y, b3.y, lora); lora = fmaf(t3.z, b3.z, lora);
                lora = fmaf(t3.w, b3.w, lora);

                const float fa = (float)c[i >> 1][na][((i & 1) << 1) | cp];
                float v = fmaf(xsv, fmaf(fa, s_ws[col], lora), s_bs[col]);
                if (fg) {
                    const float u = v * v * v;
                    const float arg = -1.5957691216f * fmaf(0.044715f, u, v);
                    v = __fdividef(v, 1.0f + __expf(arg));
                }
                v2[cp] = v;
            }
            *(float2*)(orow + colb) = make_float2(v2[0], v2[1]);
        }
    }
}

extern "C" void kernel_launch(void* const* d_in, const int* in_sizes, int n_in,
                              void* d_out, int out_size) {
    // Size-based resolution; accepts element counts OR byte counts, int8 OR
    // int32 encodings of the two big tensors.
    const void*  x    = nullptr;
    const void*  wgt  = nullptr;
    const float* bias = nullptr;
    const float* xsc  = nullptr;
    const float* wsc  = nullptr;
    const float* la   = nullptr;
    const float* lb   = nullptr;
    const unsigned int* fg = nullptr;
    int seenB = 0, seenL = 0;
    for (int i = 0; i < n_in; i++) {
        const long long s = in_sizes[i];
        if (s == 33554432 || s == 134217728) x = d_in[i];
        else if (s == 16777216 || s == 67108864) wgt = d_in[i];
        else if (s == 8192 || s == 32768) xsc = (const float*)d_in[i];
        else if (s == 65536 || s == 262144) {
            if (seenL++ == 0) la = (const float*)d_in[i];
            else              lb = (const float*)d_in[i];
        } else if (s == 4096 || s == 16384) {
            if (seenB++ == 0) bias = (const float*)d_in[i];
            else              wsc  = (const float*)d_in[i];
        } else if (s == 1 || s == 4) {
            fg = (const unsigned int*)d_in[i];
        }
    }
    if (!x || !wgt || !bias || !xsc || !wsc || !la || !lb) {
        x    = d_in[0];
        wgt  = d_in[1];
        bias = (const float*)d_in[2];
        xsc  = (const float*)d_in[3];
        wsc  = (const float*)d_in[4];
        la   = (const float*)d_in[5];
        lb   = (const float*)d_in[6];
        fg   = (n_in >= 8) ? (const unsigned int*)d_in[7] : nullptr;
    }
    float* out = (float*)d_out;

    cudaFuncSetAttribute(gemm_kernel, cudaFuncAttributeMaxDynamicSharedMemorySize, SMEM_DYN);

    int8_t* gx8; int8_t* gw8;
    cudaGetSymbolAddress((void**)&gx8, g_x8);
    cudaGetSymbolAddress((void**)&gw8, g_w8);

    detect_kernel<<<1, 256>>>(x, wgt);
    pack_kernel<<<(M_TOK * INF / 4 + 255) / 256, 256>>>(gx8, x, M_TOK * INF / 4, 0);
    pack_kernel<<<(OUTF * INF / 4 + 255) / 256, 256>>>(gw8, wgt, OUTF * INF / 4, 1);
    prep_t_kernel<<<M_TOK / 8, 256>>>(la);
    gemm_kernel<<<dim3(OUTF / BN, M_TOK / BM), 256, SMEM_DYN>>>(
        out, xsc, wsc, bias, lb, fg);
}

// round 9
// speedup vs baseline: 3.8385x; 3.8385x over previous
#include <cuda_runtime.h>
#include <cuda_bf16.h>
#include <cstdint>
#include <cstddef>

#define M_TOK 8192
#define INF   4096
#define OUTF  4096
#define RK    16
#define BM    128
#define BN    128
#define BKE   64                  // K elems per stage row (bf16) = 128 bytes
#define KITERS (INF / BKE)        // 64
#define STAGES 4
#define A_BYTES (BM * 128)        // 16384
#define STAGE_BYTES (2 * A_BYTES) // 32768
#define SMEM_DYN (STAGES * STAGE_BYTES)  // 131072

// ---- device scratch ----
__device__ float g_T[(size_t)M_TOK * RK];
__device__ __align__(1024) __nv_bfloat16 g_xb[(size_t)M_TOK * INF];  // x as bf16 (exact)
__device__ __align__(1024) __nv_bfloat16 g_wb[(size_t)OUTF * INF];   // w as bf16 (exact)

// ---------------- helpers ----------------
static __device__ __forceinline__ uint32_t smem_u32(const void* p) {
    uint32_t a;
    asm("{ .reg .u64 t; cvta.to.shared.u64 t, %1; cvt.u32.u64 %0, t; }" : "=r"(a) : "l"(p));
    return a;
}
static __device__ __forceinline__ uint32_t swz128(uint32_t off) {
    return off ^ ((off >> 3) & 0x70);
}
static __device__ __forceinline__ void cp16(uint32_t d, const void* s) {
    asm volatile("cp.async.cg.shared.global [%0], [%1], 16;" :: "r"(d), "l"(s) : "memory");
}
#define CP_COMMIT() asm volatile("cp.async.commit_group;" ::: "memory")
#define CP_WAIT(n)  asm volatile("cp.async.wait_group %0;" :: "n"(n) : "memory")

static __device__ __forceinline__ uint32_t lds32(uint32_t a) {
    uint32_t v;
    asm volatile("ld.shared.b32 %0, [%1];" : "=r"(v) : "r"(a));
    return v;
}
static __device__ __forceinline__ void hmma(float& d0, float& d1, float& d2, float& d3,
                                            uint32_t a0, uint32_t a1, uint32_t a2, uint32_t a3,
                                            uint32_t b0, uint32_t b1) {
    asm volatile(
        "mma.sync.aligned.m16n8k16.row.col.f32.bf16.bf16.f32 "
        "{%0,%1,%2,%3}, {%4,%5,%6,%7}, {%8,%9}, {%0,%1,%2,%3};"
        : "+f"(d0), "+f"(d1), "+f"(d2), "+f"(d3)
        : "r"(a0), "r"(a1), "r"(a2), "r"(a3), "r"(b0), "r"(b1));
}

// int32-promotion detection: sample 8 words; int32-encoded int8 => all in [-300,300].
static __device__ __forceinline__ int detect_fmt(const void* p, unsigned mask) {
    const int* pi = (const int*)p;
    int cnt = 0;
#pragma unroll
    for (int j = 0; j < 8; j++) {
        int v = pi[((unsigned)(j * 1048573 + 97) * 2654435761u) & mask];
        cnt += (v >= -300 && v <= 300);
    }
    return cnt >= 6;
}

// ---- pack x -> bf16 AND compute T = x @ lora_a^T in one pass ----
__global__ void __launch_bounds__(128) pack_prep_x(const void* __restrict__ xp,
                                                   const float* __restrict__ la) {
    __shared__ int s_fmt;
    __shared__ float red[4][RK];
    const int t = threadIdx.x;
    const int m = blockIdx.x;
    if (t == 0) s_fmt = detect_fmt(xp, 8388607u);  // <8M int32 slots valid either way
    __syncthreads();
    const int fmt = s_fmt;

    __nv_bfloat16* __restrict__ dst = g_xb + (size_t)m * INF;
    float acc[RK];
#pragma unroll
    for (int r = 0; r < RK; r++) acc[r] = 0.f;

#pragma unroll
    for (int j = 0; j < 8; j++) {
        const int k0 = j * 512 + t * 4;
        float f0, f1, f2, f3;
        if (fmt) {
            int4 v = ((const int4*)xp)[((size_t)m * INF + k0) >> 2];
            f0 = (float)v.x; f1 = (float)v.y; f2 = (float)v.z; f3 = (float)v.w;
        } else {
            char4 c = ((const char4*)xp)[((size_t)m * INF + k0) >> 2];
            f0 = (float)c.x; f1 = (float)c.y; f2 = (float)c.z; f3 = (float)c.w;
        }
        ((__nv_bfloat162*)dst)[k0 >> 1]       = __floats2bfloat162_rn(f0, f1);
        ((__nv_bfloat162*)dst)[(k0 >> 1) + 1] = __floats2bfloat162_rn(f2, f3);
#pragma unroll
        for (int r = 0; r < RK; r++) {
            float4 a = *(const float4*)(la + (size_t)r * INF + k0);
            acc[r] = fmaf(f0, a.x, acc[r]);
            acc[r] = fmaf(f1, a.y, acc[r]);
            acc[r] = fmaf(f2, a.z, acc[r]);
            acc[r] = fmaf(f3, a.w, acc[r]);
        }
    }
#pragma unroll
    for (int off = 16; off >= 1; off >>= 1)
#pragma unroll
        for (int r = 0; r < RK; r++)
            acc[r] += __shfl_xor_sync(0xffffffffu, acc[r], off);
    const int wid = t >> 5, lane = t & 31;
    if (lane == 0)
#pragma unroll
        for (int r = 0; r < RK; r++) red[wid][r] = acc[r];
    __syncthreads();
    if (t < RK)
        g_T[(size_t)m * RK + t] = red[0][t] + red[1][t] + red[2][t] + red[3][t];
}

// ---- pack w -> bf16 ----
__global__ void __launch_bounds__(128) pack_w(const void* __restrict__ wp) {
    __shared__ int s_fmt;
    const int t = threadIdx.x;
    const int n = blockIdx.x;
    if (t == 0) s_fmt = detect_fmt(wp, 4194303u);
    __syncthreads();
    const int fmt = s_fmt;
    __nv_bfloat16* __restrict__ dst = g_wb + (size_t)n * INF;
#pragma unroll
    for (int j = 0; j < 8; j++) {
        const int k0 = j * 512 + t * 4;
        float f0, f1, f2, f3;
        if (fmt) {
            int4 v = ((const int4*)wp)[((size_t)n * INF + k0) >> 2];
            f0 = (float)v.x; f1 = (float)v.y; f2 = (float)v.z; f3 = (float)v.w;
        } else {
            char4 c = ((const char4*)wp)[((size_t)n * INF + k0) >> 2];
            f0 = (float)c.x; f1 = (float)c.y; f2 = (float)c.z; f3 = (float)c.w;
        }
        ((__nv_bfloat162*)dst)[k0 >> 1]       = __floats2bfloat162_rn(f0, f1);
        ((__nv_bfloat162*)dst)[(k0 >> 1) + 1] = __floats2bfloat162_rn(f2, f3);
    }
}

// ---------------- main: bf16 HMMA GEMM + fused LoRA/bias/GELU epilogue -----
static __device__ __forceinline__ void load_stage(uint32_t base, int m0, int n0, int kt, int t) {
    const __nv_bfloat16* __restrict__ gA = g_xb + (size_t)m0 * INF + kt * BKE;
    const __nv_bfloat16* __restrict__ gB = g_wb + (size_t)n0 * INF + kt * BKE;
#pragma unroll
    for (int i = 0; i < 4; i++) {
        int c = t + 256 * i;                      // 0..1023
        int row = c >> 3, j = c & 7;
        cp16(base + swz128((uint32_t)(row * 128 + j * 16)),
             (const void*)(gA + (size_t)row * INF + j * 8));
    }
#pragma unroll
    for (int i = 0; i < 4; i++) {
        int c = t + 256 * i;
        int row = c >> 3, j = c & 7;
        cp16(base + (uint32_t)A_BYTES + swz128((uint32_t)(row * 128 + j * 16)),
             (const void*)(gB + (size_t)row * INF + j * 8));
    }
}

__global__ void __launch_bounds__(256, 1)
gemm_kernel(float* __restrict__ out,
            const float* __restrict__ xsc, const float* __restrict__ wsc,
            const float* __restrict__ bias, const float* __restrict__ lora_b,
            const unsigned int* __restrict__ fgp) {
    extern __shared__ __align__(1024) unsigned char dsm[];

    const int t = threadIdx.x;
    const int wid = t >> 5, lane = t & 31;
    const int g = lane >> 2, tig = lane & 3;      // mma fragment coords
    const int wm = wid & 3, wn = wid >> 2;        // 4 warps in M, 2 in N
    const int m_warp = wm * 32, n_warp = wn * 64;
    const int n0 = blockIdx.x * BN, m0 = blockIdx.y * BM;

    const uint32_t smem0 = smem_u32(dsm);

    float c[2][8][4];
#pragma unroll
    for (int am = 0; am < 2; am++)
#pragma unroll
        for (int na = 0; na < 8; na++)
#pragma unroll
            for (int f = 0; f < 4; f++) c[am][na][f] = 0.f;

#pragma unroll
    for (int s = 0; s < 3; s++) {
        load_stage(smem0 + s * STAGE_BYTES, m0, n0, s, t);
        CP_COMMIT();
    }

    for (int kt = 0; kt < KITERS; kt++) {
        CP_WAIT(2);
        __syncthreads();   // also orders reuse of stage (kt+3)&3 == (kt-1)&3

        const uint32_t sA = smem0 + (uint32_t)(kt & 3) * STAGE_BYTES;
        const uint32_t sB = sA + (uint32_t)A_BYTES;

#pragma unroll
        for (int ks = 0; ks < 4; ks++) {
            const int kb = ks * 32 + tig * 4;     // byte offset (16 bf16 per ks)

            // bf16 m16n8k16 fragments — byte-identical addressing to the s8 k32 case:
            //  a0:(row g, kb) a1:(row g+8, kb) a2:(row g, kb+16) a3:(row g+8, kb+16)
            uint32_t a[2][4];
#pragma unroll
            for (int am = 0; am < 2; am++) {
                const int r0 = m_warp + am * 16 + g;
                a[am][0] = lds32(sA + swz128((uint32_t)(r0 * 128 + kb)));
                a[am][1] = lds32(sA + swz128((uint32_t)((r0 + 8) * 128 + kb)));
                a[am][2] = lds32(sA + swz128((uint32_t)(r0 * 128 + kb + 16)));
                a[am][3] = lds32(sA + swz128((uint32_t)((r0 + 8) * 128 + kb + 16)));
            }
            uint32_t b[8][2];
#pragma unroll
            for (int na = 0; na < 8; na++) {
                const int nr = n_warp + na * 8 + g;
                b[na][0] = lds32(sB + swz128((uint32_t)(nr * 128 + kb)));
                b[na][1] = lds32(sB + swz128((uint32_t)(nr * 128 + kb + 16)));
            }
#pragma unroll
            for (int am = 0; am < 2; am++)
#pragma unroll
                for (int na = 0; na < 8; na++)
                    hmma(c[am][na][0], c[am][na][1], c[am][na][2], c[am][na][3],
                         a[am][0], a[am][1], a[am][2], a[am][3],
                         b[na][0], b[na][1]);
        }

        if (kt + 3 < KITERS)
            load_stage(smem0 + (uint32_t)((kt + 3) & 3) * STAGE_BYTES, m0, n0, kt + 3, t);
        CP_COMMIT();
    }

    CP_WAIT(0);
    __syncthreads();

    // ---- epilogue ----
    float* Ts   = (float*)dsm;                    // [128][16]
    float* Bs   = (float*)(dsm + 8192);           // [128][16]
    float* s_xs = (float*)(dsm + 16384);
    float* s_ws = (float*)(dsm + 16896);
    float* s_bs = (float*)(dsm + 17408);

    {
        const float4* tg = (const float4*)(g_T + (size_t)m0 * RK);
        const float4* bg = (const float4*)(lora_b + (size_t)n0 * RK);
        float4* ts4 = (float4*)Ts;
        float4* bs4 = (float4*)Bs;
#pragma unroll
        for (int i = 0; i < 2; i++) {
            ts4[t + 256 * i] = tg[t + 256 * i];
            bs4[t + 256 * i] = bg[t + 256 * i];
        }
        if (t < 128) {
            s_xs[t] = xsc[m0 + t];
            s_ws[t] = wsc[n0 + t];
            s_bs[t] = bias[n0 + t];
        }
    }
    __syncthreads();

    const bool fg = fgp ? (fgp[0] != 0u) : true;

#pragma unroll
    for (int i = 0; i < 4; i++) {
        const int rowT = m_warp + (i >> 1) * 16 + (i & 1) * 8 + g;
        const float xsv = s_xs[rowT];
        const float4* tp = (const float4*)(Ts + rowT * 16);
        const float4 t0 = tp[0], t1 = tp[1], t2 = tp[2], t3 = tp[3];
        float* __restrict__ orow = out + (size_t)(m0 + rowT) * OUTF + n0;

#pragma unroll
        for (int na = 0; na < 8; na++) {
            const int colb = n_warp + na * 8 + 2 * tig;
            float v2[2];
#pragma unroll
            for (int cp = 0; cp < 2; cp++) {
                const int col = colb + cp;
                const float4* bp = (const float4*)(Bs + col * 16);
                const float4 b0 = bp[0], b1 = bp[1], b2 = bp[2], b3 = bp[3];
                float lora = t0.x * b0.x;
                lora = fmaf(t0.y, b0.y, lora); lora = fmaf(t0.z, b0.z, lora);
                lora = fmaf(t0.w, b0.w, lora); lora = fmaf(t1.x, b1.x, lora);
                lora = fmaf(t1.y, b1.y, lora); lora = fmaf(t1.z, b1.z, lora);
                lora = fmaf(t1.w, b1.w, lora); lora = fmaf(t2.x, b2.x, lora);
                lora = fmaf(t2.y, b2.y, lora); lora = fmaf(t2.z, b2.z, lora);
                lora = fmaf(t2.w, b2.w, lora); lora = fmaf(t3.x, b3.x, lora);
                lora = fmaf(t3.y, b3.y, lora); lora = fmaf(t3.z, b3.z, lora);
                lora = fmaf(t3.w, b3.w, lora);

                const float fa = c[i >> 1][na][((i & 1) << 1) | cp];
                float v = fmaf(xsv, fmaf(fa, s_ws[col], lora), s_bs[col]);
                if (fg) {
                    const float u = v * v * v;
                    const float arg = -1.5957691216f * fmaf(0.044715f, u, v);
                    v = __fdividef(v, 1.0f + __expf(arg));
                }
                v2[cp] = v;
            }
            *(float2*)(orow + colb) = make_float2(v2[0], v2[1]);
        }
    }
}

extern "C" void kernel_launch(void* const* d_in, const int* in_sizes, int n_in,
                              void* d_out, int out_size) {
    const void*  x    = nullptr;
    const void*  wgt  = nullptr;
    const float* bias = nullptr;
    const float* xsc  = nullptr;
    const float* wsc  = nullptr;
    const float* la   = nullptr;
    const float* lb   = nullptr;
    const unsigned int* fg = nullptr;
    int seenB = 0, seenL = 0;
    for (int i = 0; i < n_in; i++) {
        const long long s = in_sizes[i];
        if (s == 33554432 || s == 134217728) x = d_in[i];
        else if (s == 16777216 || s == 67108864) wgt = d_in[i];
        else if (s == 8192 || s == 32768) xsc = (const float*)d_in[i];
        else if (s == 65536 || s == 262144) {
            if (seenL++ == 0) la = (const float*)d_in[i];
            else              lb = (const float*)d_in[i];
        } else if (s == 4096 || s == 16384) {
            if (seenB++ == 0) bias = (const float*)d_in[i];
            else              wsc  = (const float*)d_in[i];
        } else if (s == 1 || s == 4) {
            fg = (const unsigned int*)d_in[i];
        }
    }
    if (!x || !wgt || !bias || !xsc || !wsc || !la || !lb) {
        x    = d_in[0];
        wgt  = d_in[1];
        bias = (const float*)d_in[2];
        xsc  = (const float*)d_in[3];
        wsc  = (const float*)d_in[4];
        la   = (const float*)d_in[5];
        lb   = (const float*)d_in[6];
        fg   = (n_in >= 8) ? (const unsigned int*)d_in[7] : nullptr;
    }
    float* out = (float*)d_out;

    cudaFuncSetAttribute(gemm_kernel, cudaFuncAttributeMaxDynamicSharedMemorySize, SMEM_DYN);

    pack_prep_x<<<M_TOK, 128>>>(x, la);
    pack_w<<<OUTF, 128>>>(wgt);
    gemm_kernel<<<dim3(OUTF / BN, M_TOK / BM), 256, SMEM_DYN>>>(
        out, xsc, wsc, bias, lb, fg);
}

// round 10
// speedup vs baseline: 4.0776x; 1.0623x over previous
#include <cuda_runtime.h>
#include <cuda_bf16.h>
#include <cstdint>
#include <cstddef>

#define M_TOK 8192
#define INF   4096
#define OUTF  4096
#define RK    16
#define BM    128
#define BN    256
#define BKE   64                  // K elems per stage row (bf16) = 128 bytes
#define KITERS (INF / BKE)        // 64
#define STAGES 3
#define A_BYTES (BM * 128)        // 16384
#define B_BYTES (BN * 128)        // 32768
#define STAGE_BYTES (A_BYTES + B_BYTES)  // 49152
#define SMEM_DYN (STAGES * STAGE_BYTES)  // 147456

// ---- device scratch ----
__device__ float g_T[(size_t)M_TOK * RK];
__device__ __align__(1024) __nv_bfloat16 g_xb[(size_t)M_TOK * INF];
__device__ __align__(1024) __nv_bfloat16 g_wb[(size_t)OUTF * INF];

// ---------------- helpers ----------------
static __device__ __forceinline__ uint32_t smem_u32(const void* p) {
    uint32_t a;
    asm("{ .reg .u64 t; cvta.to.shared.u64 t, %1; cvt.u32.u64 %0, t; }" : "=r"(a) : "l"(p));
    return a;
}
static __device__ __forceinline__ uint32_t swz128(uint32_t off) {
    return off ^ ((off >> 3) & 0x70);
}
static __device__ __forceinline__ void cp16(uint32_t d, const void* s) {
    asm volatile("cp.async.cg.shared.global [%0], [%1], 16;" :: "r"(d), "l"(s) : "memory");
}
#define CP_COMMIT() asm volatile("cp.async.commit_group;" ::: "memory")
#define CP_WAIT(n)  asm volatile("cp.async.wait_group %0;" :: "n"(n) : "memory")

static __device__ __forceinline__ void ldsm4(uint32_t& r0, uint32_t& r1, uint32_t& r2,
                                             uint32_t& r3, uint32_t addr) {
    asm volatile("ldmatrix.sync.aligned.m8n8.x4.shared.b16 {%0,%1,%2,%3}, [%4];"
                 : "=r"(r0), "=r"(r1), "=r"(r2), "=r"(r3) : "r"(addr));
}
static __device__ __forceinline__ void hmma(float& d0, float& d1, float& d2, float& d3,
                                            uint32_t a0, uint32_t a1, uint32_t a2, uint32_t a3,
                                            uint32_t b0, uint32_t b1) {
    asm volatile(
        "mma.sync.aligned.m16n8k16.row.col.f32.bf16.bf16.f32 "
        "{%0,%1,%2,%3}, {%4,%5,%6,%7}, {%8,%9}, {%0,%1,%2,%3};"
        : "+f"(d0), "+f"(d1), "+f"(d2), "+f"(d3)
        : "r"(a0), "r"(a1), "r"(a2), "r"(a3), "r"(b0), "r"(b1));
}

// int32-promotion detection: int32-encoded int8 values all lie in [-300, 300].
static __device__ __forceinline__ int detect_fmt(const void* p, unsigned mask) {
    const int* pi = (const int*)p;
    int cnt = 0;
#pragma unroll
    for (int j = 0; j < 8; j++) {
        int v = pi[((unsigned)(j * 1048573 + 97) * 2654435761u) & mask];
        cnt += (v >= -300 && v <= 300);
    }
    return cnt >= 6;
}

// ---- pack x -> bf16 AND compute T = x @ lora_a^T in one pass ----
__global__ void __launch_bounds__(128) pack_prep_x(const void* __restrict__ xp,
                                                   const float* __restrict__ la) {
    __shared__ int s_fmt;
    __shared__ float red[4][RK];
    const int t = threadIdx.x;
    const int m = blockIdx.x;
    if (t == 0) s_fmt = detect_fmt(xp, 8388607u);
    __syncthreads();
    const int fmt = s_fmt;

    __nv_bfloat16* __restrict__ dst = g_xb + (size_t)m * INF;
    float acc[RK];
#pragma unroll
    for (int r = 0; r < RK; r++) acc[r] = 0.f;

#pragma unroll
    for (int j = 0; j < 8; j++) {
        const int k0 = j * 512 + t * 4;
        float f0, f1, f2, f3;
        if (fmt) {
            int4 v = ((const int4*)xp)[((size_t)m * INF + k0) >> 2];
            f0 = (float)v.x; f1 = (float)v.y; f2 = (float)v.z; f3 = (float)v.w;
        } else {
            char4 c = ((const char4*)xp)[((size_t)m * INF + k0) >> 2];
            f0 = (float)c.x; f1 = (float)c.y; f2 = (float)c.z; f3 = (float)c.w;
        }
        ((__nv_bfloat162*)dst)[k0 >> 1]       = __floats2bfloat162_rn(f0, f1);
        ((__nv_bfloat162*)dst)[(k0 >> 1) + 1] = __floats2bfloat162_rn(f2, f3);
#pragma unroll
        for (int r = 0; r < RK; r++) {
            float4 a = *(const float4*)(la + (size_t)r * INF + k0);
            acc[r] = fmaf(f0, a.x, acc[r]);
            acc[r] = fmaf(f1, a.y, acc[r]);
            acc[r] = fmaf(f2, a.z, acc[r]);
            acc[r] = fmaf(f3, a.w, acc[r]);
        }
    }
#pragma unroll
    for (int off = 16; off >= 1; off >>= 1)
#pragma unroll
        for (int r = 0; r < RK; r++)
            acc[r] += __shfl_xor_sync(0xffffffffu, acc[r], off);
    const int wid = t >> 5, lane = t & 31;
    if (lane == 0)
#pragma unroll
        for (int r = 0; r < RK; r++) red[wid][r] = acc[r];
    __syncthreads();
    if (t < RK)
        g_T[(size_t)m * RK + t] = red[0][t] + red[1][t] + red[2][t] + red[3][t];
}

// ---- pack w -> bf16 ----
__global__ void __launch_bounds__(128) pack_w(const void* __restrict__ wp) {
    __shared__ int s_fmt;
    const int t = threadIdx.x;
    const int n = blockIdx.x;
    if (t == 0) s_fmt = detect_fmt(wp, 4194303u);
    __syncthreads();
    const int fmt = s_fmt;
    __nv_bfloat16* __restrict__ dst = g_wb + (size_t)n * INF;
#pragma unroll
    for (int j = 0; j < 8; j++) {
        const int k0 = j * 512 + t * 4;
        float f0, f1, f2, f3;
        if (fmt) {
            int4 v = ((const int4*)wp)[((size_t)n * INF + k0) >> 2];
            f0 = (float)v.x; f1 = (float)v.y; f2 = (float)v.z; f3 = (float)v.w;
        } else {
            char4 c = ((const char4*)wp)[((size_t)n * INF + k0) >> 2];
            f0 = (float)c.x; f1 = (float)c.y; f2 = (float)c.z; f3 = (float)c.w;
        }
        ((__nv_bfloat162*)dst)[k0 >> 1]       = __floats2bfloat162_rn(f0, f1);
        ((__nv_bfloat162*)dst)[(k0 >> 1) + 1] = __floats2bfloat162_rn(f2, f3);
    }
}

// ---------------- main: bf16 HMMA GEMM, CTA 128x256, warp 64x64 ----------
static __device__ __forceinline__ void load_stage(uint32_t base, int m0, int n0, int kt, int t) {
    const __nv_bfloat16* __restrict__ gA = g_xb + (size_t)m0 * INF + kt * BKE;
    const __nv_bfloat16* __restrict__ gB = g_wb + (size_t)n0 * INF + kt * BKE;
#pragma unroll
    for (int i = 0; i < 4; i++) {                 // A: 1024 chunks of 16B
        int c = t + 256 * i;
        int row = c >> 3, j = c & 7;
        cp16(base + swz128((uint32_t)(row * 128 + j * 16)),
             (const void*)(gA + (size_t)row * INF + j * 8));
    }
#pragma unroll
    for (int i = 0; i < 8; i++) {                 // B: 2048 chunks of 16B
        int c = t + 256 * i;
        int row = c >> 3, j = c & 7;
        cp16(base + (uint32_t)A_BYTES + swz128((uint32_t)(row * 128 + j * 16)),
             (const void*)(gB + (size_t)row * INF + j * 8));
    }
}

__global__ void __launch_bounds__(256, 1)
gemm_kernel(float* __restrict__ out,
            const float* __restrict__ xsc, const float* __restrict__ wsc,
            const float* __restrict__ bias, const float* __restrict__ lora_b,
            const unsigned int* __restrict__ fgp) {
    extern __shared__ __align__(1024) unsigned char dsm[];

    const int t = threadIdx.x;
    const int wid = t >> 5, lane = t & 31;
    const int g = lane >> 2, tig = lane & 3;
    const int wm = wid & 1, wn = wid >> 1;        // 2 warps in M, 4 in N
    const int m_warp = wm * 64, n_warp = wn * 64;
    const int n0 = blockIdx.x * BN, m0 = blockIdx.y * BM;

    const uint32_t smem0 = smem_u32(dsm);

    float c[4][8][4];                             // 4 m16 atoms x 8 n8 octets
#pragma unroll
    for (int am = 0; am < 4; am++)
#pragma unroll
        for (int na = 0; na < 8; na++)
#pragma unroll
            for (int f = 0; f < 4; f++) c[am][na][f] = 0.f;

#pragma unroll
    for (int s = 0; s < 2; s++) {
        load_stage(smem0 + s * STAGE_BYTES, m0, n0, s, t);
        CP_COMMIT();
    }

    int kslot = 0;
    for (int kt = 0; kt < KITERS; kt++) {
        CP_WAIT(1);
        __syncthreads();

        const uint32_t sA = smem0 + (uint32_t)kslot * STAGE_BYTES;
        const uint32_t sB = sA + (uint32_t)A_BYTES;

#pragma unroll
        for (int ks = 0; ks < 4; ks++) {
            // A: 4 m16 atoms via ldmatrix.x4 (mapping cross-validated vs direct LDS)
            uint32_t a[4][4];
#pragma unroll
            for (int am = 0; am < 4; am++) {
                int row = m_warp + am * 16 + (((lane >> 3) & 1) * 8) + (lane & 7);
                int col = ks * 32 + ((lane >> 4) * 16);
                ldsm4(a[am][0], a[am][1], a[am][2], a[am][3],
                      sA + swz128((uint32_t)(row * 128 + col)));
            }
            // B: 8 n8 octets via 4 ldmatrix.x4
            uint32_t b[8][2];
#pragma unroll
            for (int p = 0; p < 4; p++) {
                int row = n_warp + p * 16 + (((lane >> 4) & 1) * 8) + (lane & 7);
                int col = ks * 32 + (((lane >> 3) & 1) * 16);
                ldsm4(b[2 * p][0], b[2 * p][1], b[2 * p + 1][0], b[2 * p + 1][1],
                      sB + swz128((uint32_t)(row * 128 + col)));
            }
#pragma unroll
            for (int am = 0; am < 4; am++)
#pragma unroll
                for (int na = 0; na < 8; na++)
                    hmma(c[am][na][0], c[am][na][1], c[am][na][2], c[am][na][3],
                         a[am][0], a[am][1], a[am][2], a[am][3],
                         b[na][0], b[na][1]);
        }

        if (kt + 2 < KITERS) {
            int ns = kslot;                        // slot being vacated next
            // write into the slot 2 ahead: (kt+2) % 3
            int ws = kslot + 2; if (ws >= STAGES) ws -= STAGES;
            load_stage(smem0 + (uint32_t)ws * STAGE_BYTES, m0, n0, kt + 2, t);
            (void)ns;
        }
        CP_COMMIT();
        if (++kslot == STAGES) kslot = 0;
    }

    CP_WAIT(0);
    __syncthreads();

    // ---- epilogue ----
    float* Ts   = (float*)dsm;                    // [128][16]
    float* Bs   = (float*)(dsm + 8192);           // [256][16]
    float* s_xs = (float*)(dsm + 24576);          // [128]
    float* s_ws = (float*)(dsm + 25088);          // [256]
    float* s_bs = (float*)(dsm + 26112);          // [256]

    {
        const float4* tg = (const float4*)(g_T + (size_t)m0 * RK);
        const float4* bg = (const float4*)(lora_b + (size_t)n0 * RK);
        float4* ts4 = (float4*)Ts;
        float4* bs4 = (float4*)Bs;
#pragma unroll
        for (int i = 0; i < 2; i++) ts4[t + 256 * i] = tg[t + 256 * i];
#pragma unroll
        for (int i = 0; i < 4; i++) bs4[t + 256 * i] = bg[t + 256 * i];
        if (t < 128) s_xs[t] = xsc[m0 + t];
        s_ws[t] = wsc[n0 + t];
        s_bs[t] = bias[n0 + t];
    }
    __syncthreads();

    const bool fg = fgp ? (fgp[0] != 0u) : true;

#pragma unroll
    for (int am = 0; am < 4; am++) {
#pragma unroll
        for (int h = 0; h < 2; h++) {
            const int rowT = m_warp + am * 16 + h * 8 + g;
            const float xsv = s_xs[rowT];
            const float4* tp = (const float4*)(Ts + rowT * 16);
            const float4 t0 = tp[0], t1 = tp[1], t2 = tp[2], t3 = tp[3];
            float* __restrict__ orow = out + (size_t)(m0 + rowT) * OUTF + n0;

#pragma unroll
            for (int na = 0; na < 8; na++) {
                const int colb = n_warp + na * 8 + 2 * tig;
                float v2[2];
#pragma unroll
                for (int cp = 0; cp < 2; cp++) {
                    const int col = colb + cp;
                    const float4* bp = (const float4*)(Bs + col * 16);
                    const float4 b0 = bp[0], b1 = bp[1], b2 = bp[2], b3 = bp[3];
                    float lora = t0.x * b0.x;
                    lora = fmaf(t0.y, b0.y, lora); lora = fmaf(t0.z, b0.z, lora);
                    lora = fmaf(t0.w, b0.w, lora); lora = fmaf(t1.x, b1.x, lora);
                    lora = fmaf(t1.y, b1.y, lora); lora = fmaf(t1.z, b1.z, lora);
                    lora = fmaf(t1.w, b1.w, lora); lora = fmaf(t2.x, b2.x, lora);
                    lora = fmaf(t2.y, b2.y, lora); lora = fmaf(t2.z, b2.z, lora);
                    lora = fmaf(t2.w, b2.w, lora); lora = fmaf(t3.x, b3.x, lora);
                    lora = fmaf(t3.y, b3.y, lora); lora = fmaf(t3.z, b3.z, lora);
                    lora = fmaf(t3.w, b3.w, lora);

                    const float fa = c[am][na][(h << 1) | cp];
                    float v = fmaf(xsv, fmaf(fa, s_ws[col], lora), s_bs[col]);
                    if (fg) {
                        const float u = v * v * v;
                        const float arg = -1.5957691216f * fmaf(0.044715f, u, v);
                        v = __fdividef(v, 1.0f + __expf(arg));
                    }
                    v2[cp] = v;
                }
                *(float2*)(orow + colb) = make_float2(v2[0], v2[1]);
            }
        }
    }
}

extern "C" void kernel_launch(void* const* d_in, const int* in_sizes, int n_in,
                              void* d_out, int out_size) {
    const void*  x    = nullptr;
    const void*  wgt  = nullptr;
    const float* bias = nullptr;
    const float* xsc  = nullptr;
    const float* wsc  = nullptr;
    const float* la   = nullptr;
    const float* lb   = nullptr;
    const unsigned int* fg = nullptr;
    int seenB = 0, seenL = 0;
    for (int i = 0; i < n_in; i++) {
        const long long s = in_sizes[i];
        if (s == 33554432 || s == 134217728) x = d_in[i];
        else if (s == 16777216 || s == 67108864) wgt = d_in[i];
        else if (s == 8192 || s == 32768) xsc = (const float*)d_in[i];
        else if (s == 65536 || s == 262144) {
            if (seenL++ == 0) la = (const float*)d_in[i];
            else              lb = (const float*)d_in[i];
        } else if (s == 4096 || s == 16384) {
            if (seenB++ == 0) bias = (const float*)d_in[i];
            else              wsc  = (const float*)d_in[i];
        } else if (s == 1 || s == 4) {
            fg = (const unsigned int*)d_in[i];
        }
    }
    if (!x || !wgt || !bias || !xsc || !wsc || !la || !lb) {
        x    = d_in[0];
        wgt  = d_in[1];
        bias = (const float*)d_in[2];
        xsc  = (const float*)d_in[3];
        wsc  = (const float*)d_in[4];
        la   = (const float*)d_in[5];
        lb   = (const float*)d_in[6];
        fg   = (n_in >= 8) ? (const unsigned int*)d_in[7] : nullptr;
    }
    float* out = (float*)d_out;

    cudaFuncSetAttribute(gemm_kernel, cudaFuncAttributeMaxDynamicSharedMemorySize, SMEM_DYN);

    pack_prep_x<<<M_TOK, 128>>>(x, la);
    pack_w<<<OUTF, 128>>>(wgt);
    gemm_kernel<<<dim3(OUTF / BN, M_TOK / BM), 256, SMEM_DYN>>>(
        out, xsc, wsc, bias, lb, fg);
}